// round 9
// baseline (speedup 1.0000x reference)
#include <cuda_runtime.h>
#include <cuda_fp16.h>
#include <cstdint>
#include <math.h>

#define EMBED 768
#define BQ    256
#define NTOT  16384
#define SCALE 0.1020620726159657f   // 96^-0.5

#define NPROJ 780        // 12 Q tiles + 768 K tiles
#define NATTN 1024       // 4 b-blocks x 256 n-blocks, 64x64 each
#define NTICK (NPROJ + NATTN)

// ---------------------------------------------------------------------------
// Device scratch (static globals — no runtime allocation)
// ---------------------------------------------------------------------------
__device__ __half g_sh_hi[NTOT*EMBED];                          // search hi
__device__ __half g_qi_hi[BQ*EMBED],   g_qi_lo[BQ*EMBED];       // query split
__device__ __half g_wk_hi[EMBED*EMBED];                         // Wk hi
__device__ __half g_wq_hi[EMBED*EMBED];                         // Wq hi
__device__ __half g_k_hi[NTOT*EMBED];                           // projected K hi
__device__ __half g_qp_hi[BQ*EMBED];                            // projected Q hi

__device__ int g_ticket;
__device__ int g_kdone[128];   // per K m-block (128 rows each): count to 6
__device__ int g_qdone[2];     // per Q m-block: count to 6

// ---------------------------------------------------------------------------
// Helpers
// ---------------------------------------------------------------------------
__device__ __forceinline__ uint32_t smem_u32(const void* p) {
    uint32_t a;
    asm("{ .reg .u64 t; cvta.to.shared.u64 t, %1; cvt.u32.u64 %0, t; }"
        : "=r"(a) : "l"(p));
    return a;
}

__device__ __forceinline__ void cp16(uint32_t dst, const void* src) {
    asm volatile("cp.async.cg.shared.global [%0], [%1], 16;" :: "r"(dst), "l"(src));
}
#define CP_COMMIT() asm volatile("cp.async.commit_group;")
#define CP_WAIT0()  asm volatile("cp.async.wait_group 0;")
#define CP_WAIT1()  asm volatile("cp.async.wait_group 1;")

__device__ __forceinline__ void ldm_x4(uint32_t& r0, uint32_t& r1, uint32_t& r2,
                                       uint32_t& r3, uint32_t addr) {
    asm volatile("ldmatrix.sync.aligned.m8n8.x4.shared.b16 {%0,%1,%2,%3}, [%4];"
                 : "=r"(r0), "=r"(r1), "=r"(r2), "=r"(r3) : "r"(addr));
}

__device__ __forceinline__ void mma_f16(float c[4], uint32_t a0, uint32_t a1,
                                        uint32_t a2, uint32_t a3,
                                        uint32_t b0, uint32_t b1) {
    asm volatile(
        "mma.sync.aligned.m16n8k16.row.col.f32.f16.f16.f32 "
        "{%0,%1,%2,%3}, {%4,%5,%6,%7}, {%8,%9}, {%0,%1,%2,%3};"
        : "+f"(c[0]), "+f"(c[1]), "+f"(c[2]), "+f"(c[3])
        : "r"(a0), "r"(a1), "r"(a2), "r"(a3), "r"(b0), "r"(b1));
}

// Packed fp32x2 FMA (Blackwell FFMA2): d = a*b + c elementwise on 2 lanes.
__device__ __forceinline__ void fma_x2(unsigned long long& d, unsigned long long a,
                                       unsigned long long b, unsigned long long c) {
    asm("fma.rn.f32x2 %0, %1, %2, %3;" : "=l"(d) : "l"(a), "l"(b), "l"(c));
}
__device__ __forceinline__ unsigned long long pack2(float lo, float hi) {
    unsigned long long d;
    asm("mov.b64 %0, {%1, %2};" : "=l"(d) : "f"(lo), "f"(hi));
    return d;
}
__device__ __forceinline__ void unpack2(float& lo, float& hi, unsigned long long v) {
    asm("mov.b64 {%0, %1}, %2;" : "=f"(lo), "=f"(hi) : "l"(v));
}

// ---------------------------------------------------------------------------
// Fused split + flag reset.
// search -> hi only; query -> hi+lo; Wk/Wq -> hi only.
// ---------------------------------------------------------------------------
#define N4S (NTOT*EMBED/4)
#define N4Q (BQ*EMBED/4)
#define N4W (EMBED*EMBED/4)

__global__ void split_all(const float* __restrict__ search,
                          const float* __restrict__ query,
                          const float* __restrict__ Wk,
                          const float* __restrict__ Wq) {
    if (blockIdx.x == 0) {          // reset queue + flags
        if (threadIdx.x == 0) g_ticket = 0;
        if (threadIdx.x < 128) g_kdone[threadIdx.x] = 0;
        if (threadIdx.x < 2)   g_qdone[threadIdx.x] = 0;
    }
    int i = blockIdx.x * blockDim.x + threadIdx.x;
    const float* src;
    __half *hi, *lo = nullptr;
    if (i < N4S)                      { src = search; hi = g_sh_hi; }
    else if ((i -= N4S) < N4Q)        { src = query;  hi = g_qi_hi; lo = g_qi_lo; }
    else if ((i -= N4Q) < N4W)        { src = Wk;     hi = g_wk_hi; }
    else if ((i -= N4W) < N4W)        { src = Wq;     hi = g_wq_hi; }
    else return;
    float4 v = ((const float4*)src)[i];
    __half h0 = __float2half(v.x), h1 = __float2half(v.y);
    __half h2 = __float2half(v.z), h3 = __float2half(v.w);
    ((__half2*)hi)[i*2]   = __halves2half2(h0, h1);
    ((__half2*)hi)[i*2+1] = __halves2half2(h2, h3);
    if (lo) {
        ((__half2*)lo)[i*2]   = __halves2half2(__float2half(v.x - __half2float(h0)),
                                               __float2half(v.y - __half2float(h1)));
        ((__half2*)lo)[i*2+1] = __halves2half2(__float2half(v.z - __half2float(h2)),
                                               __float2half(v.w - __half2float(h3)));
    }
}

// ---------------------------------------------------------------------------
// Fused persistent kernel: proj tiles (tickets 0..779) + attn tiles (780..).
// 296 CTAs x 128 threads, 2 CTA/SM (all resident -> spin-safe).
// smem: proj buffers A/Alo/B @ buf*49152 (96K) | attn 3x16K @ 0/16K/32K
//       | params @98304 | ticket @98560.
// ---------------------------------------------------------------------------
struct TileView {
    const __half *Ahi, *Alo, *Bhi;
    __half* Ohi;
    const float* bias;
    int m0, n0, nterms;
};

__device__ __forceinline__ void tile_params(int t, const float* bk,
                                            const float* bq, TileView& v) {
    if (t < 12) {
        v.Ahi = g_qi_hi; v.Alo = g_qi_lo; v.Bhi = g_wq_hi;
        v.Ohi = g_qp_hi; v.bias = bq;
        v.m0 = (t / 6) * 128; v.n0 = (t % 6) * 128; v.nterms = 2;
    } else {
        const int tt = t - 12;
        v.Ahi = g_sh_hi; v.Alo = nullptr; v.Bhi = g_wk_hi;
        v.Ohi = g_k_hi;  v.bias = bk;
        v.m0 = (tt / 6) * 128; v.n0 = (tt % 6) * 128; v.nterms = 1;
    }
}

__device__ __forceinline__ void proj_issue(uint32_t sb, int buf, int tid,
                                           const TileView& v, int k0) {
    const uint32_t base = sb + (uint32_t)buf * 49152u;
#pragma unroll
    for (int i = 0; i < 8; ++i) {
        const int seg = tid + 128 * i;
        const int row = seg >> 3, sg = seg & 7;
        const uint32_t off = (uint32_t)row * 128u +
                             ((uint32_t)(sg * 16) ^ (uint32_t)((row & 7) << 4));
        cp16(base + off, v.Ahi + (size_t)(v.m0 + row) * EMBED + k0 + sg * 8);
        if (v.nterms == 2)
            cp16(base + 16384u + off, v.Alo + (size_t)(v.m0 + row) * EMBED + k0 + sg * 8);
        cp16(base + 32768u + off, v.Bhi + (size_t)(v.n0 + row) * EMBED + k0 + sg * 8);
    }
    CP_COMMIT();
}

__global__ __launch_bounds__(128, 2)
void fused_tc(const float* __restrict__ bk, const float* __restrict__ bq,
              const float* __restrict__ W1, const float* __restrict__ b1,
              const float* __restrict__ W2, const float* __restrict__ b2,
              float* __restrict__ outp)
{
    extern __shared__ char dsm[];
    const uint32_t sb = smem_u32(dsm);
    float* s_w1 = (float*)(dsm + 98304);
    float* s_mi = (float*)(dsm + 98432);
    int*   s_tk = (int*)(dsm + 98560);
    const int tid = threadIdx.x, wid = tid >> 5, lane = tid & 31;
    const int wm = wid & 1, wn = wid >> 1;

    if (tid < 32) s_w1[tid] = W1[tid] * SCALE;
    if (tid < 4)  { s_mi[tid] = b1[tid]; s_mi[4 + tid] = W2[tid]; }
    if (tid == 8) s_mi[8] = b2[0];

    const int g  = lane >> 3;
    const int gr = ((g & 1) << 3) + (lane & 7);   // A-frag row sel
    const int gk = (g >> 1) << 4;                 // A-frag k sel
    const int hr = ((g >> 1) << 3) + (lane & 7);  // B-frag row sel
    const int hk = (g & 1) << 4;                  // B-frag k sel

    __syncthreads();

    for (;;) {
        if (tid == 0) *s_tk = atomicAdd(&g_ticket, 1);
        __syncthreads();
        const int t = *s_tk;
        if (t >= NTICK) break;

        if (t < NPROJ) {
            // ============================ PROJ TILE ============================
            TileView v;
            tile_params(t, bk, bq, v);
            const int nterms = v.nterms;

            float c[4][8][4];
#pragma unroll
            for (int i = 0; i < 4; ++i)
#pragma unroll
                for (int j = 0; j < 8; ++j)
#pragma unroll
                    for (int k = 0; k < 4; ++k) c[i][j][k] = 0.0f;

            proj_issue(sb, 0, tid, v, 0);
            CP_WAIT0();
            __syncthreads();

#pragma unroll 1
            for (int ch = 0; ch < 12; ++ch) {
                const int b = ch & 1;
                if (ch + 1 < 12) proj_issue(sb, b ^ 1, tid, v, (ch + 1) * 64);

                const uint32_t Ab = sb + (uint32_t)b * 49152u;
                const uint32_t Bb = Ab + 32768u;
#pragma unroll
                for (int ks = 0; ks < 4; ++ks) {
                    uint32_t bf[8][2];
#pragma unroll
                    for (int p = 0; p < 4; ++p) {
                        const int r = wn * 64 + p * 16 + hr;
                        const int kb = ks * 32 + hk;
                        uint32_t r0, r1, r2, r3;
                        ldm_x4(r0, r1, r2, r3,
                               Bb + (uint32_t)r * 128u + (uint32_t)(kb ^ ((r & 7) << 4)));
                        bf[2*p][0] = r0;   bf[2*p][1] = r1;
                        bf[2*p+1][0] = r2; bf[2*p+1][1] = r3;
                    }
#pragma unroll 1
                    for (int tt = 0; tt < nterms; ++tt) {
                        const uint32_t At = Ab + (uint32_t)tt * 16384u;
                        uint32_t a[4][4];
#pragma unroll
                        for (int mt = 0; mt < 4; ++mt) {
                            const int r = wm * 64 + mt * 16 + gr;
                            const int kb = ks * 32 + gk;
                            ldm_x4(a[mt][0], a[mt][1], a[mt][2], a[mt][3],
                                   At + (uint32_t)r * 128u + (uint32_t)(kb ^ ((r & 7) << 4)));
                        }
#pragma unroll
                        for (int mt = 0; mt < 4; ++mt)
#pragma unroll
                            for (int nt = 0; nt < 8; ++nt)
                                mma_f16(c[mt][nt], a[mt][0], a[mt][1], a[mt][2], a[mt][3],
                                        bf[nt][0], bf[nt][1]);
                    }
                }
                if (ch + 1 < 12) CP_WAIT0();
                __syncthreads();
            }

            // Epilogue: bias + fp16 hi store
#pragma unroll
            for (int mt = 0; mt < 4; ++mt) {
#pragma unroll
                for (int nt = 0; nt < 8; ++nt) {
                    const int col = v.n0 + wn * 64 + nt * 8 + (lane & 3) * 2;
                    const float bc0 = __ldg(v.bias + col), bc1 = __ldg(v.bias + col + 1);
#pragma unroll
                    for (int h = 0; h < 2; ++h) {
                        const int row = v.m0 + wm * 64 + mt * 16 + (lane >> 2) + h * 8;
                        float x0 = c[mt][nt][2*h]   + bc0;
                        float x1 = c[mt][nt][2*h+1] + bc1;
                        *(__half2*)(v.Ohi + (size_t)row * EMBED + col) =
                            __halves2half2(__float2half(x0), __float2half(x1));
                    }
                }
            }

            // publish: all stores visible, then count the tile
            __threadfence();
            __syncthreads();
            if (tid == 0) {
                if (t < 12) atomicAdd(&g_qdone[t / 6], 1);
                else        atomicAdd(&g_kdone[(t - 12) / 6], 1);
            }
        } else {
            // ============================ ATTN TILE ============================
            const int u  = t - NPROJ;
            const int bb = u & 3, nb = u >> 2;
            const int m0 = bb * 64, n0 = nb * 64;

            // wait for producers (K m-block nb>>1, Q m-block bb>>1)
            if (tid == 0) {
                while (atomicAdd(&g_kdone[nb >> 1], 0) < 6) __nanosleep(64);
                while (atomicAdd(&g_qdone[bb >> 1], 0) < 6) __nanosleep(64);
            }
            __syncthreads();

            float c[2][4][4];
            unsigned long long hp[2][4][4][2];   // (mt, nt, j, kpair) fp32x2
#pragma unroll
            for (int i = 0; i < 2; ++i)
#pragma unroll
                for (int j = 0; j < 4; ++j) {
#pragma unroll
                    for (int k = 0; k < 4; ++k) c[i][j][k] = 0.0f;
#pragma unroll
                    for (int l = 0; l < 4; ++l)
#pragma unroll
                        for (int p = 0; p < 2; ++p) hp[i][j][l][p] = 0ull;
                }

            auto issue = [&](int chunk) {
                const int k0 = chunk * 64;
                const uint32_t base = sb + (uint32_t)(chunk % 3) * 16384u;
#pragma unroll
                for (int i = 0; i < 4; ++i) {        // Q 512 segs + K 512 segs
                    const int seg = tid + 128 * i;
                    const int row = seg >> 3, sg = seg & 7;
                    const uint32_t off = (uint32_t)row * 128u +
                                         ((uint32_t)(sg * 16) ^ (uint32_t)((row & 7) << 4));
                    cp16(base + off,         g_qp_hi + (size_t)(m0 + row) * EMBED + k0 + sg * 8);
                    cp16(base + 8192u + off, g_k_hi  + (size_t)(n0 + row) * EMBED + k0 + sg * 8);
                }
                CP_COMMIT();
            };

            issue(0);
            issue(1);

#pragma unroll 1
            for (int ch = 0; ch < 12; ++ch) {
                if (ch < 11) CP_WAIT1(); else CP_WAIT0();
                __syncthreads();
                if (ch + 2 < 12) issue(ch + 2);

                const uint32_t Ab = sb + (uint32_t)(ch % 3) * 16384u;
                const uint32_t Bb = Ab + 8192u;
#pragma unroll
                for (int ks = 0; ks < 4; ++ks) {
                    uint32_t bf[4][2];
#pragma unroll
                    for (int p = 0; p < 2; ++p) {
                        const int r = wn * 32 + p * 16 + hr;
                        const int kb = ks * 32 + hk;
                        uint32_t r0, r1, r2, r3;
                        ldm_x4(r0, r1, r2, r3,
                               Bb + (uint32_t)r * 128u + (uint32_t)(kb ^ ((r & 7) << 4)));
                        bf[2*p][0] = r0;   bf[2*p][1] = r1;
                        bf[2*p+1][0] = r2; bf[2*p+1][1] = r3;
                    }
                    uint32_t a[2][4];
#pragma unroll
                    for (int mt = 0; mt < 2; ++mt) {
                        const int r = wm * 32 + mt * 16 + gr;
                        const int kb = ks * 32 + gk;
                        ldm_x4(a[mt][0], a[mt][1], a[mt][2], a[mt][3],
                               Ab + (uint32_t)r * 128u + (uint32_t)(kb ^ ((r & 7) << 4)));
                    }
#pragma unroll
                    for (int mt = 0; mt < 2; ++mt)
#pragma unroll
                        for (int nt = 0; nt < 4; ++nt)
                            mma_f16(c[mt][nt], a[mt][0], a[mt][1], a[mt][2], a[mt][3],
                                    bf[nt][0], bf[nt][1]);

                    const int s = ch * 4 + ks;
                    if ((s % 6) == 5) {           // head fold via packed FFMA2
                        const int h = s / 6;
                        unsigned long long w01 = pack2(s_w1[h],      s_w1[h]);
                        unsigned long long w1p = pack2(s_w1[8 + h],  s_w1[8 + h]);
                        unsigned long long w2p = pack2(s_w1[16 + h], s_w1[16 + h]);
                        unsigned long long w3p = pack2(s_w1[24 + h], s_w1[24 + h]);
#pragma unroll
                        for (int mt = 0; mt < 2; ++mt)
#pragma unroll
                            for (int nt = 0; nt < 4; ++nt)
#pragma unroll
                                for (int p = 0; p < 2; ++p) {
                                    unsigned long long bv =
                                        pack2(c[mt][nt][2*p], c[mt][nt][2*p + 1]);
                                    fma_x2(hp[mt][nt][0][p], w01, bv, hp[mt][nt][0][p]);
                                    fma_x2(hp[mt][nt][1][p], w1p, bv, hp[mt][nt][1][p]);
                                    fma_x2(hp[mt][nt][2][p], w2p, bv, hp[mt][nt][2][p]);
                                    fma_x2(hp[mt][nt][3][p], w3p, bv, hp[mt][nt][3][p]);
                                    c[mt][nt][2*p] = 0.0f;
                                    c[mt][nt][2*p + 1] = 0.0f;
                                }
                    }
                }
            }

            // Epilogue: GELU(erf) + W2, float2 stores
            const float b10 = s_mi[0], b11 = s_mi[1], b12 = s_mi[2], b13 = s_mi[3];
            const float w20 = s_mi[4], w21 = s_mi[5], w22 = s_mi[6], w23 = s_mi[7];
            const float bb2 = s_mi[8];
            const float inv_sqrt2 = 0.70710678118654752f;
#pragma unroll
            for (int mt = 0; mt < 2; ++mt)
#pragma unroll
                for (int nt = 0; nt < 4; ++nt) {
                    const int col = n0 + wn * 32 + nt * 8 + (lane & 3) * 2;
#pragma unroll
                    for (int h = 0; h < 2; ++h) {
                        const int row = m0 + wm * 32 + mt * 16 + (lane >> 2) + h * 8;
                        float o[2];
#pragma unroll
                        for (int e = 0; e < 2; ++e) {
                            const int k = 2 * h + e;       // kpair = h, lane = e
                            float y0, y1, y2, y3, z;
                            unpack2(y0, z, hp[mt][nt][0][h]); if (e) y0 = z;
                            unpack2(y1, z, hp[mt][nt][1][h]); if (e) y1 = z;
                            unpack2(y2, z, hp[mt][nt][2][h]); if (e) y2 = z;
                            unpack2(y3, z, hp[mt][nt][3][h]); if (e) y3 = z;
                            (void)k;
                            float x0 = y0 + b10, x1 = y1 + b11;
                            float x2 = y2 + b12, x3 = y3 + b13;
                            float g0 = 0.5f * x0 * (1.0f + erff(x0 * inv_sqrt2));
                            float g1 = 0.5f * x1 * (1.0f + erff(x1 * inv_sqrt2));
                            float g2 = 0.5f * x2 * (1.0f + erff(x2 * inv_sqrt2));
                            float g3 = 0.5f * x3 * (1.0f + erff(x3 * inv_sqrt2));
                            float s = bb2;
                            s = fmaf(w20, g0, s); s = fmaf(w21, g1, s);
                            s = fmaf(w22, g2, s); s = fmaf(w23, g3, s);
                            o[e] = s;
                        }
                        *(float2*)(outp + (size_t)row * NTOT + col) = make_float2(o[0], o[1]);
                    }
                }
        }
    }
}

// ---------------------------------------------------------------------------
extern "C" void kernel_launch(void* const* d_in, const int* in_sizes, int n_in,
                              void* d_out, int out_size)
{
    const float* query  = (const float*)d_in[0];
    const float* search = (const float*)d_in[1];
    const float* Wq     = (const float*)d_in[2];
    const float* bq     = (const float*)d_in[3];
    const float* Wk     = (const float*)d_in[4];
    const float* bk     = (const float*)d_in[5];
    const float* W1     = (const float*)d_in[6];
    const float* b1     = (const float*)d_in[7];
    const float* W2     = (const float*)d_in[8];
    const float* b2     = (const float*)d_in[9];
    float* out = (float*)d_out;

    cudaFuncSetAttribute(fused_tc, cudaFuncAttributeMaxDynamicSharedMemorySize, 98816);

    const int total4 = N4S + N4Q + 2 * N4W;
    split_all<<<(total4 + 255) / 256, 256>>>(search, query, Wk, Wq);

    fused_tc<<<296, 128, 98816>>>(bk, bq, W1, b1, W2, b2, out);
}